// round 9
// baseline (speedup 1.0000x reference)
#include <cuda_runtime.h>
#include <math.h>

#define N_NODES 12288
#define F_IN    1433
#define E_EDGES 196608
#define H1      32
#define H2      16
#define C_OUT   7

// ---------------- scratch (static __device__, no allocations) ----------------
__device__ __align__(16) float g_xw[N_NODES * H1];   // x @ W1
__device__ __align__(16) float g_z[N_NODES * H1];    // GCN pre-aggregation accumulator
__device__ __align__(16) float g_h[N_NODES * H1];    // GCN layer output (post relu)
__device__ __align__(16) float g_agg[N_NODES * H1];  // SAGE neighbor sum
__device__ float g_deg[N_NODES];       // degree over col (ei1) + self loop
__device__ float g_cnt[N_NODES];       // count over src (ei0)
__device__ float g_dis[N_NODES];       // deg^-0.5
__device__ int   g_is64;               // edge_index dtype flag

// Fetch edge endpoint robustly w.r.t. int32 vs int64 storage.
__device__ __forceinline__ int edge_at(const int* ei32, int is64, int idx) {
    if (is64) return __ldg(&ei32[2 * idx]);  // little-endian low word of int64
    return __ldg(&ei32[idx]);
}

// ---------------- K0: detect dtype of edge_index ----------------
__global__ void detect_kernel(const int* __restrict__ ei32) {
    // int64 values < 2^31 => odd words all zero. int32 data: odd words are
    // random indices in [0, 12288) -> essentially impossible to all be zero.
    if (threadIdx.x == 0 && blockIdx.x == 0) {
        int any = 0;
        for (int k = 0; k < 256; k++) any |= ei32[2 * k + 1];
        g_is64 = (any == 0) ? 1 : 0;
    }
}

// ---------------- K1: init ----------------
__global__ void init_kernel() {
    int idx = blockIdx.x * blockDim.x + threadIdx.x;
    if (idx < N_NODES * H1) g_agg[idx] = 0.0f;
    if (idx < N_NODES) { g_deg[idx] = 1.0f; g_cnt[idx] = 0.0f; }  // self loop in deg
}

// ---------------- K2: degree / count histogram ----------------
__global__ void hist_kernel(const int* __restrict__ ei32) {
    int e = blockIdx.x * blockDim.x + threadIdx.x;
    if (e < E_EDGES) {
        int is64 = g_is64;
        int r = edge_at(ei32, is64, e);             // edge_index[0][e]
        int c = edge_at(ei32, is64, E_EDGES + e);   // edge_index[1][e]
        if ((unsigned)r < N_NODES) atomicAdd(&g_cnt[r], 1.0f);
        if ((unsigned)c < N_NODES) atomicAdd(&g_deg[c], 1.0f);
    }
}

// ---------------- K3: xw = x @ W1 ; fused epilogue writes g_xw, g_z(self-loop), g_dis ----------
// BM=96 rows, BN=32 cols, BK=32. 256 threads, thread tile 3 rows x 4 cols.
// grid = 12288/96 = 128 blocks (one wave on 148 SMs).
#define BM 96
#define BK 32
__global__ __launch_bounds__(256, 1)
void gemm_kernel(const float* __restrict__ x, const float* __restrict__ W1) {
    __shared__ float xs[BM][BK + 1];
    __shared__ float ws[BK][H1 + 1];

    const int rowBase = blockIdx.x * BM;
    const int tx = threadIdx.x & 7;    // col quad: cols tx*4..tx*4+3
    const int ty = threadIdx.x >> 3;   // row triple: rows ty*3..ty*3+2
    const int ty3 = ty * 3;
    const int tx4 = tx * 4;

    float acc[3][4];
#pragma unroll
    for (int i = 0; i < 3; i++)
#pragma unroll
        for (int j = 0; j < 4; j++) acc[i][j] = 0.0f;

    const int nTiles = (F_IN + BK - 1) / BK;  // 45
    for (int kt = 0; kt < nTiles; kt++) {
        const int kBase = kt * BK;
        // load x tile: 96x32, 12 elements per thread, coalesced per warp-row
#pragma unroll
        for (int i = 0; i < 12; i++) {
            int idx = threadIdx.x + i * 256;
            int r = idx >> 5, l = idx & 31;
            int kg = kBase + l;
            xs[r][l] = (kg < F_IN) ? x[(size_t)(rowBase + r) * F_IN + kg] : 0.0f;
        }
        // load W1 tile: 32x32, 4 per thread
#pragma unroll
        for (int i = 0; i < 4; i++) {
            int idx = threadIdx.x + i * 256;
            int k = idx >> 5, c = idx & 31;
            int kg = kBase + k;
            ws[k][c] = (kg < F_IN) ? W1[(size_t)kg * H1 + c] : 0.0f;
        }
        __syncthreads();

#pragma unroll
        for (int k = 0; k < BK; k++) {
            float a0 = xs[ty3 + 0][k];
            float a1 = xs[ty3 + 1][k];
            float a2 = xs[ty3 + 2][k];
            float b0 = ws[k][tx4 + 0];
            float b1 = ws[k][tx4 + 1];
            float b2 = ws[k][tx4 + 2];
            float b3 = ws[k][tx4 + 3];
            acc[0][0] += a0 * b0; acc[0][1] += a0 * b1; acc[0][2] += a0 * b2; acc[0][3] += a0 * b3;
            acc[1][0] += a1 * b0; acc[1][1] += a1 * b1; acc[1][2] += a1 * b2; acc[1][3] += a1 * b3;
            acc[2][0] += a2 * b0; acc[2][1] += a2 * b1; acc[2][2] += a2 * b2; acc[2][3] += a2 * b3;
        }
        __syncthreads();
    }

    // fused epilogue: g_xw = acc; dis = rsqrt(deg); g_z = dis*acc (self-loop term); g_dis
#pragma unroll
    for (int i = 0; i < 3; i++) {
        int row = rowBase + ty3 + i;
        float dis = rsqrtf(g_deg[row]);
        if (tx == 0) g_dis[row] = dis;
#pragma unroll
        for (int j = 0; j < 4; j++) {
            g_xw[(size_t)row * H1 + tx4 + j] = acc[i][j];
            g_z[(size_t)row * H1 + tx4 + j] = dis * acc[i][j];
        }
    }
}

// ---------------- K5: GCN scatter: z[r] += dis[c]*xw[c] ----------------
__global__ __launch_bounds__(512)
void gcn_scatter(const int* __restrict__ ei32) {
    int t = blockIdx.x * blockDim.x + threadIdx.x;
    int e = t >> 5, lane = t & 31;
    if (e >= E_EDGES) return;
    int is64 = g_is64;
    int r = 0, c = 0;
    if (lane == 0) {
        r = edge_at(ei32, is64, e);
        c = edge_at(ei32, is64, E_EDGES + e);
    }
    r = __shfl_sync(0xffffffffu, r, 0);
    c = __shfl_sync(0xffffffffu, c, 0);
    if ((unsigned)r < N_NODES && (unsigned)c < N_NODES) {
        float v = __ldg(&g_dis[c]) * __ldg(&g_xw[c * H1 + lane]);
        atomicAdd(&g_z[r * H1 + lane], v);
    }
}

// ---------------- K6: h = relu(dis[i]*z + b1) ----------------
__global__ void hrelu_kernel(const float* __restrict__ b1) {
    int idx = blockIdx.x * blockDim.x + threadIdx.x;
    if (idx >= N_NODES * H1) return;
    int i = idx >> 5, j = idx & 31;
    g_h[idx] = fmaxf(g_dis[i] * g_z[idx] + b1[j], 0.0f);
}

// ---------------- K7: SAGE scatter: agg[r] += h[c] ----------------
__global__ __launch_bounds__(512)
void sage_scatter(const int* __restrict__ ei32) {
    int t = blockIdx.x * blockDim.x + threadIdx.x;
    int e = t >> 5, lane = t & 31;
    if (e >= E_EDGES) return;
    int is64 = g_is64;
    int r = 0, c = 0;
    if (lane == 0) {
        r = edge_at(ei32, is64, e);
        c = edge_at(ei32, is64, E_EDGES + e);
    }
    r = __shfl_sync(0xffffffffu, r, 0);
    c = __shfl_sync(0xffffffffu, c, 0);
    if ((unsigned)r < N_NODES && (unsigned)c < N_NODES)
        atomicAdd(&g_agg[r * H1 + lane], __ldg(&g_h[c * H1 + lane]));
}

// ---------------- K8: head ----------------
__global__ __launch_bounds__(256)
void final_kernel(const float* __restrict__ Wl, const float* __restrict__ bl,
                  const float* __restrict__ Wr, const float* __restrict__ br,
                  const float* __restrict__ W3, const float* __restrict__ b3,
                  float* __restrict__ out) {
    __shared__ float sWl[H1 * H2], sWr[H1 * H2], sW3[H2 * C_OUT];
    __shared__ float sbl[H2], sbr[H2], sb3[C_OUT];
    for (int i = threadIdx.x; i < H1 * H2; i += 256) { sWl[i] = Wl[i]; sWr[i] = Wr[i]; }
    if (threadIdx.x < H2 * C_OUT) sW3[threadIdx.x] = W3[threadIdx.x];
    if (threadIdx.x < H2) { sbl[threadIdx.x] = bl[threadIdx.x]; sbr[threadIdx.x] = br[threadIdx.x]; }
    if (threadIdx.x < C_OUT) sb3[threadIdx.x] = b3[threadIdx.x];
    __syncthreads();

    int n = blockIdx.x * blockDim.x + threadIdx.x;
    if (n >= N_NODES) return;

    float h[H1], ag[H1];
    const float4* hp = (const float4*)&g_h[(size_t)n * H1];
    const float4* ap = (const float4*)&g_agg[(size_t)n * H1];
#pragma unroll
    for (int i = 0; i < H1 / 4; i++) {
        float4 v = hp[i];
        h[i * 4 + 0] = v.x; h[i * 4 + 1] = v.y; h[i * 4 + 2] = v.z; h[i * 4 + 3] = v.w;
        float4 a = ap[i];
        ag[i * 4 + 0] = a.x; ag[i * 4 + 1] = a.y; ag[i * 4 + 2] = a.z; ag[i * 4 + 3] = a.w;
    }
    float cnt = g_cnt[n];
    float cs = (cnt > 0.0f) ? (1.0f / cnt) : 0.0f;
#pragma unroll
    for (int k = 0; k < H1; k++) ag[k] *= cs;

    float o[H2];
    float ss = 0.0f;
#pragma unroll
    for (int j = 0; j < H2; j++) {
        float v = sbl[j] + sbr[j];
#pragma unroll
        for (int k = 0; k < H1; k++)
            v += h[k] * sWl[k * H2 + j] + ag[k] * sWr[k * H2 + j];
        v = fmaxf(v, 0.0f);
        o[j] = v;
        ss += v * v;
    }
    float inv = 1.0f / (sqrtf(ss) + 1e-6f);
#pragma unroll
    for (int j = 0; j < H2; j++) o[j] *= inv;

    float lg[C_OUT];
    float m = -1e30f;
#pragma unroll
    for (int j = 0; j < C_OUT; j++) {
        float v = sb3[j];
#pragma unroll
        for (int k = 0; k < H2; k++) v += o[k] * sW3[k * C_OUT + j];
        lg[j] = v;
        m = fmaxf(m, v);
    }
    float es = 0.0f;
#pragma unroll
    for (int j = 0; j < C_OUT; j++) { lg[j] = expf(lg[j] - m); es += lg[j]; }
    float invs = 1.0f / es;
#pragma unroll
    for (int j = 0; j < C_OUT; j++) out[(size_t)n * C_OUT + j] = lg[j] * invs;
}

// ---------------- launch ----------------
extern "C" void kernel_launch(void* const* d_in, const int* in_sizes, int n_in,
                              void* d_out, int out_size) {
    const float* x  = (const float*)d_in[0];
    const int*   ei = (const int*)d_in[1];   // int32 or int64 (autodetected)
    const float* W1 = (const float*)d_in[2];
    const float* b1 = (const float*)d_in[3];
    const float* Wl = (const float*)d_in[4];
    const float* bl = (const float*)d_in[5];
    const float* Wr = (const float*)d_in[6];
    const float* br = (const float*)d_in[7];
    const float* W3 = (const float*)d_in[8];
    const float* b3 = (const float*)d_in[9];
    float* out = (float*)d_out;

    const int NH = N_NODES * H1;
    detect_kernel<<<1, 1>>>(ei);
    init_kernel<<<(NH + 255) / 256, 256>>>();
    hist_kernel<<<(E_EDGES + 255) / 256, 256>>>(ei);
    gemm_kernel<<<N_NODES / BM, 256>>>(x, W1);       // also writes g_z self-loop + g_dis
    gcn_scatter<<<(E_EDGES * 32) / 512, 512>>>(ei);
    hrelu_kernel<<<(NH + 255) / 256, 256>>>(b1);
    sage_scatter<<<(E_EDGES * 32) / 512, 512>>>(ei);
    final_kernel<<<(N_NODES + 255) / 256, 256>>>(Wl, bl, Wr, br, W3, b3, out);
}